// round 12
// baseline (speedup 1.0000x reference)
#include <cuda_runtime.h>

// AttentionOptimizer: out = spins - LR*(grads + SMOOTH*g_smooth) + noise
// g_smooth = conv3(u)/conv3(v),  u = g*exp(-BETA*|g|), v = exp(-BETA*|g|),
// separable per-axis kernel w[d] = exp(-0.0125*(d*2/19)^2) = exp(-0.05 d^2/361).
//
// R12 = R11 + LDS shaves:
//   - phase-2 V taps loaded pairwise via LDS.128 (V pairs are contiguous
//     float2s, 16B-aligned for even j) -> 20 -> 10 tap loads per thread
//   - 4 accumulators in phases 2/3 (5-deep fma2 chains)
// Structure unchanged: one CTA per (b,y_out), 400 threads, constant weights
// (uniform LDCU in phase 1), smem weights for phases 2/3, 2 barriers,
// packed f32x2 math, streaming epilogue store.

#define LLAT 20
#define PLANE 400                 // LLAT*LLAT
#define NPTS 8000                 // LLAT^3
#define NEG2_LOG2E 2.8853900817779268f   // 2*log2(e)

// CW2[i] = {w,w} with w = exp(-0.05*(i-19)^2/361)  (hand-evaluated)
__constant__ float2 CW2[2 * LLAT - 1] = {
    {0.9512294245f, 0.9512294245f}, {0.9561166621f, 0.9561166621f},
    {0.9607628249f, 0.9607628249f}, {0.9651641734f, 0.9651641734f},
    {0.9693171397f, 0.9693171397f}, {0.9732183487f, 0.9732183487f},
    {0.9768646216f, 0.9768646216f}, {0.9802529795f, 0.9802529795f},
    {0.9833806481f, 0.9833806481f}, {0.9862450604f, 0.9862450604f},
    {0.9888438596f, 0.9888438596f}, {0.9911749058f, 0.9911749058f},
    {0.9932362740f, 0.9932362740f}, {0.9950262606f, 0.9950262606f},
    {0.9965433840f, 0.9965433840f}, {0.9977863872f, 0.9977863872f},
    {0.9987542392f, 0.9987542392f}, {0.9994461368f, 0.9994461368f},
    {0.9998615054f, 0.9998615054f}, {1.0000000000f, 1.0000000000f},
    {0.9998615054f, 0.9998615054f}, {0.9994461368f, 0.9994461368f},
    {0.9987542392f, 0.9987542392f}, {0.9977863872f, 0.9977863872f},
    {0.9965433840f, 0.9965433840f}, {0.9950262606f, 0.9950262606f},
    {0.9932362740f, 0.9932362740f}, {0.9911749058f, 0.9911749058f},
    {0.9888438596f, 0.9888438596f}, {0.9862450604f, 0.9862450604f},
    {0.9833806481f, 0.9833806481f}, {0.9802529795f, 0.9802529795f},
    {0.9768646216f, 0.9768646216f}, {0.9732183487f, 0.9732183487f},
    {0.9693171397f, 0.9693171397f}, {0.9651641734f, 0.9651641734f},
    {0.9607628249f, 0.9607628249f}, {0.9561166621f, 0.9561166621f},
    {0.9512294245f, 0.9512294245f}
};

// Packed f32x2 FMA (sm_103a): d = a*b + c on both lanes.
static __device__ __forceinline__ float2 fma2(float2 a, float2 b, float2 c) {
    float2 d;
    asm("fma.rn.f32x2 %0, %1, %2, %3;"
        : "=l"(*reinterpret_cast<unsigned long long*>(&d))
        : "l"(*reinterpret_cast<unsigned long long*>(&a)),
          "l"(*reinterpret_cast<unsigned long long*>(&b)),
          "l"(*reinterpret_cast<unsigned long long*>(&c)));
    return d;
}

static __device__ __forceinline__ float2 add2(float2 a, float2 b) {
    return make_float2(a.x + b.x, a.y + b.y);
}

static __device__ __forceinline__ void stg_cs(float* p, float v) {
    asm volatile("st.global.cs.f32 [%0], %1;" :: "l"(p), "f"(v) : "memory");
}

__global__ void __launch_bounds__(PLANE, 1)
attn_opt_fused(const float* __restrict__ grads,
               const float* __restrict__ spins,
               const float* __restrict__ noise,
               float* __restrict__ out)
{
    __shared__ float2 V[PLANE];
    __shared__ float2 T[PLANE];
    __shared__ float2 w2[2 * LLAT - 1];   // smem copy for per-thread indices

    const int t  = threadIdx.x;              // t = xp*20 + zp
    const int yo = blockIdx.x;               // output y-plane
    const int b  = blockIdx.y;
    const int xp = t / LLAT;
    const int zp = t - xp * LLAT;

    // w2 copy first: STS drains long before the phase-1->2 barrier.
    if (t < 2 * LLAT - 1) w2[t] = CW2[t];

    // Head of the dependency chain: the 20-deep y-column of grads.
    const float* gcol = grads + b * NPTS + xp * PLANE + zp;
    float gc[LLAT];
#pragma unroll
    for (int yp = 0; yp < LLAT; yp++) gc[yp] = gcol[yp * LLAT];

    // Epilogue operands — explicit LDGs (constant-index registers only).
    const int gi = b * NPTS + xp * PLANE + yo * LLAT + zp;
    const float s_v = spins[gi];
    const float n_v = noise[gi];
    const float g_v = grads[gi];

    // Phase 1: y-reduction, weights via UNIFORM constant loads (no barrier).
    float2 a0 = make_float2(0.0f, 0.0f), a1 = make_float2(0.0f, 0.0f);
    float2 a2 = make_float2(0.0f, 0.0f), a3 = make_float2(0.0f, 0.0f);
#pragma unroll
    for (int yp = 0; yp < LLAT; yp += 4) {
        const float e0 = exp2f(-NEG2_LOG2E * fabsf(gc[yp]));
        const float e1 = exp2f(-NEG2_LOG2E * fabsf(gc[yp + 1]));
        const float e2 = exp2f(-NEG2_LOG2E * fabsf(gc[yp + 2]));
        const float e3 = exp2f(-NEG2_LOG2E * fabsf(gc[yp + 3]));
        a0 = fma2(make_float2(gc[yp] * e0, e0),
                  CW2[(LLAT - 1) + yo - yp], a0);           // uniform LDCU
        a1 = fma2(make_float2(gc[yp + 1] * e1, e1),
                  CW2[(LLAT - 1) + yo - (yp + 1)], a1);
        a2 = fma2(make_float2(gc[yp + 2] * e2, e2),
                  CW2[(LLAT - 1) + yo - (yp + 2)], a2);
        a3 = fma2(make_float2(gc[yp + 3] * e3, e3),
                  CW2[(LLAT - 1) + yo - (yp + 3)], a3);
    }
    V[t] = add2(add2(a0, a1), add2(a2, a3));

    // Precompute epilogue base while the barrier drains / MUFUs finish.
    const float base = s_v + n_v - 0.05f * g_v;
    __syncthreads();   // covers V and the w2 copy

    // Phase 2: z-conv via LDS.128 V-pairs (16B-aligned for even j).
    a0 = make_float2(0.0f, 0.0f); a1 = make_float2(0.0f, 0.0f);
    a2 = make_float2(0.0f, 0.0f); a3 = make_float2(0.0f, 0.0f);
#pragma unroll
    for (int j = 0; j < LLAT; j += 4) {
        const float4 v01 = *reinterpret_cast<const float4*>(&V[xp * LLAT + j]);
        const float4 v23 = *reinterpret_cast<const float4*>(&V[xp * LLAT + j + 2]);
        a0 = fma2(make_float2(v01.x, v01.y), w2[(LLAT - 1) + zp - j],       a0);
        a1 = fma2(make_float2(v01.z, v01.w), w2[(LLAT - 1) + zp - (j + 1)], a1);
        a2 = fma2(make_float2(v23.x, v23.y), w2[(LLAT - 1) + zp - (j + 2)], a2);
        a3 = fma2(make_float2(v23.z, v23.w), w2[(LLAT - 1) + zp - (j + 3)], a3);
    }
    T[t] = add2(add2(a0, a1), add2(a2, a3));
    __syncthreads();

    // Phase 3: x-conv. R[xp][zp] = sum_j w[xp-j] T[j][zp]  (stride-20 taps)
    a0 = make_float2(0.0f, 0.0f); a1 = make_float2(0.0f, 0.0f);
    a2 = make_float2(0.0f, 0.0f); a3 = make_float2(0.0f, 0.0f);
#pragma unroll
    for (int j = 0; j < LLAT; j += 4) {
        a0 = fma2(T[j * LLAT + zp],       w2[(LLAT - 1) + xp - j],       a0);
        a1 = fma2(T[(j + 1) * LLAT + zp], w2[(LLAT - 1) + xp - (j + 1)], a1);
        a2 = fma2(T[(j + 2) * LLAT + zp], w2[(LLAT - 1) + xp - (j + 2)], a2);
        a3 = fma2(T[(j + 3) * LLAT + zp], w2[(LLAT - 1) + xp - (j + 3)], a3);
    }
    const float2 r = add2(add2(a0, a1), add2(a2, a3));

    // Epilogue: out = base - 0.5*(u/v)  (streaming store)
    stg_cs(out + gi, base - 0.5f * __fdividef(r.x, r.y));
}

extern "C" void kernel_launch(void* const* d_in, const int* in_sizes, int n_in,
                              void* d_out, int out_size)
{
    const float* grads = (const float*)d_in[0];
    const float* spins = (const float*)d_in[1];
    // d_in[2] = pos: unused — lattice geometry is known analytically.
    const float* noise = (const float*)d_in[3];
    float* out = (float*)d_out;

    const int B = in_sizes[0] / NPTS;
    dim3 grid(LLAT, B);
    attn_opt_fused<<<grid, PLANE>>>(grads, spins, noise, out);
}

// round 13
// speedup vs baseline: 1.3544x; 1.3544x over previous
#include <cuda_runtime.h>

// AttentionOptimizer: out = spins - LR*(grads + SMOOTH*g_smooth) + noise
// g_smooth = conv3(u)/conv3(v),  u = g*exp(-BETA*|g|), v = exp(-BETA*|g|),
// separable per-axis kernel w[d] = exp(-0.0125*(d*2/19)^2) = exp(-0.05 d^2/361).
//
// R13: warp-per-row layout. Block = 640 threads; warp w = lattice row xp,
// lane = zp (lanes 20-31 idle). Phase 1 -> phase 2 needs only intra-warp
// visibility (z-conv reads the warp's own row), so the first __syncthreads
// becomes __syncwarp: each warp starts its z-conv as soon as ITS OWN DRAM
// column lands (no cross-warp straggler wait). One full barrier remains
// before the x-conv. Rows padded to stride 32 float2.

#define LLAT 20
#define PLANE 400                 // LLAT*LLAT
#define NPTS 8000                 // LLAT^3
#define RSTR 32                   // padded row stride (float2)
#define NTHR 640                  // 20 warps * 32
#define NEG2_LOG2E 2.8853900817779268f   // 2*log2(e)

// CW2[i] = {w,w} with w = exp(-0.05*(i-19)^2/361)  (hand-evaluated)
__constant__ float2 CW2[2 * LLAT - 1] = {
    {0.9512294245f, 0.9512294245f}, {0.9561166621f, 0.9561166621f},
    {0.9607628249f, 0.9607628249f}, {0.9651641734f, 0.9651641734f},
    {0.9693171397f, 0.9693171397f}, {0.9732183487f, 0.9732183487f},
    {0.9768646216f, 0.9768646216f}, {0.9802529795f, 0.9802529795f},
    {0.9833806481f, 0.9833806481f}, {0.9862450604f, 0.9862450604f},
    {0.9888438596f, 0.9888438596f}, {0.9911749058f, 0.9911749058f},
    {0.9932362740f, 0.9932362740f}, {0.9950262606f, 0.9950262606f},
    {0.9965433840f, 0.9965433840f}, {0.9977863872f, 0.9977863872f},
    {0.9987542392f, 0.9987542392f}, {0.9994461368f, 0.9994461368f},
    {0.9998615054f, 0.9998615054f}, {1.0000000000f, 1.0000000000f},
    {0.9998615054f, 0.9998615054f}, {0.9994461368f, 0.9994461368f},
    {0.9987542392f, 0.9987542392f}, {0.9977863872f, 0.9977863872f},
    {0.9965433840f, 0.9965433840f}, {0.9950262606f, 0.9950262606f},
    {0.9932362740f, 0.9932362740f}, {0.9911749058f, 0.9911749058f},
    {0.9888438596f, 0.9888438596f}, {0.9862450604f, 0.9862450604f},
    {0.9833806481f, 0.9833806481f}, {0.9802529795f, 0.9802529795f},
    {0.9768646216f, 0.9768646216f}, {0.9732183487f, 0.9732183487f},
    {0.9693171397f, 0.9693171397f}, {0.9651641734f, 0.9651641734f},
    {0.9607628249f, 0.9607628249f}, {0.9561166621f, 0.9561166621f},
    {0.9512294245f, 0.9512294245f}
};

// Packed f32x2 FMA (sm_103a): d = a*b + c on both lanes.
static __device__ __forceinline__ float2 fma2(float2 a, float2 b, float2 c) {
    float2 d;
    asm("fma.rn.f32x2 %0, %1, %2, %3;"
        : "=l"(*reinterpret_cast<unsigned long long*>(&d))
        : "l"(*reinterpret_cast<unsigned long long*>(&a)),
          "l"(*reinterpret_cast<unsigned long long*>(&b)),
          "l"(*reinterpret_cast<unsigned long long*>(&c)));
    return d;
}

static __device__ __forceinline__ float2 add2(float2 a, float2 b) {
    return make_float2(a.x + b.x, a.y + b.y);
}

static __device__ __forceinline__ void stg_cs(float* p, float v) {
    asm volatile("st.global.cs.f32 [%0], %1;" :: "l"(p), "f"(v) : "memory");
}

__global__ void __launch_bounds__(NTHR, 1)
attn_opt_fused(const float* __restrict__ grads,
               const float* __restrict__ spins,
               const float* __restrict__ noise,
               float* __restrict__ out)
{
    __shared__ float2 V[LLAT * RSTR];     // row xp at V[xp*32 + zp]
    __shared__ float2 T[LLAT * RSTR];
    __shared__ float2 w2[2 * LLAT - 1];

    const int t    = threadIdx.x;
    const int xp   = t >> 5;              // warp = lattice row
    const int zp   = t & 31;              // lane = z index
    const bool act = (zp < LLAT);
    const int yo   = blockIdx.x;          // output y-plane
    const int b    = blockIdx.y;

    // w2 copy first (covered by the single full barrier below).
    if (t < 2 * LLAT - 1) w2[t] = CW2[t];

    float2 acc = make_float2(0.0f, 0.0f);
    int gi = 0;
    float base = 0.0f;

    if (act) {
        // Head of the dependency chain: the 20-deep y-column of grads.
        const float* gcol = grads + b * NPTS + xp * PLANE + zp;
        float gc[LLAT];
#pragma unroll
        for (int yp = 0; yp < LLAT; yp++) gc[yp] = gcol[yp * LLAT];

        // Epilogue operands.
        gi = b * NPTS + xp * PLANE + yo * LLAT + zp;
        const float s_v = spins[gi];
        const float n_v = noise[gi];
        const float g_v = grads[gi];

        // Phase 1: y-reduction, weights via UNIFORM constant loads.
        float2 a0 = make_float2(0.0f, 0.0f), a1 = make_float2(0.0f, 0.0f);
        float2 a2 = make_float2(0.0f, 0.0f), a3 = make_float2(0.0f, 0.0f);
#pragma unroll
        for (int yp = 0; yp < LLAT; yp += 4) {
            const float e0 = exp2f(-NEG2_LOG2E * fabsf(gc[yp]));
            const float e1 = exp2f(-NEG2_LOG2E * fabsf(gc[yp + 1]));
            const float e2 = exp2f(-NEG2_LOG2E * fabsf(gc[yp + 2]));
            const float e3 = exp2f(-NEG2_LOG2E * fabsf(gc[yp + 3]));
            a0 = fma2(make_float2(gc[yp] * e0, e0),
                      CW2[(LLAT - 1) + yo - yp], a0);
            a1 = fma2(make_float2(gc[yp + 1] * e1, e1),
                      CW2[(LLAT - 1) + yo - (yp + 1)], a1);
            a2 = fma2(make_float2(gc[yp + 2] * e2, e2),
                      CW2[(LLAT - 1) + yo - (yp + 2)], a2);
            a3 = fma2(make_float2(gc[yp + 3] * e3, e3),
                      CW2[(LLAT - 1) + yo - (yp + 3)], a3);
        }
        V[xp * RSTR + zp] = add2(add2(a0, a1), add2(a2, a3));
        base = s_v + n_v - 0.05f * g_v;
    }

    // Intra-warp visibility only: this warp wrote the whole row it reads.
    __syncwarp();

    if (act) {
        // Phase 2: z-conv on own row (broadcast LDS, no cross-warp wait).
        float2 a0 = make_float2(0.0f, 0.0f), a1 = make_float2(0.0f, 0.0f);
#pragma unroll
        for (int j = 0; j < LLAT; j += 2) {
            a0 = fma2(V[xp * RSTR + j],     w2[(LLAT - 1) + zp - j],       a0);
            a1 = fma2(V[xp * RSTR + j + 1], w2[(LLAT - 1) + zp - (j + 1)], a1);
        }
        T[xp * RSTR + zp] = add2(a0, a1);
    }

    __syncthreads();   // x-conv crosses rows; also covers w2 copy

    if (act) {
        // Phase 3: x-conv. R = sum_j w[xp-j] * T[j][zp]
        float2 a0 = make_float2(0.0f, 0.0f), a1 = make_float2(0.0f, 0.0f);
#pragma unroll
        for (int j = 0; j < LLAT; j += 2) {
            a0 = fma2(T[j * RSTR + zp],       w2[(LLAT - 1) + xp - j],       a0);
            a1 = fma2(T[(j + 1) * RSTR + zp], w2[(LLAT - 1) + xp - (j + 1)], a1);
        }
        const float2 r = add2(a0, a1);

        // Epilogue: out = base - 0.5*(u/v)  (streaming store)
        stg_cs(out + gi, base - 0.5f * __fdividef(r.x, r.y));
    }
}

extern "C" void kernel_launch(void* const* d_in, const int* in_sizes, int n_in,
                              void* d_out, int out_size)
{
    const float* grads = (const float*)d_in[0];
    const float* spins = (const float*)d_in[1];
    // d_in[2] = pos: unused — lattice geometry is known analytically.
    const float* noise = (const float*)d_in[3];
    float* out = (float*)d_out;

    const int B = in_sizes[0] / NPTS;
    dim3 grid(LLAT, B);
    attn_opt_fused<<<grid, NTHR>>>(grads, spins, noise, out);
}